// round 7
// baseline (speedup 1.0000x reference)
#include <cuda_runtime.h>
#include <math.h>

#define NNODES 2048
#define NBATCH 16
#define NEDGES 12288
#define DDENSE 6144
#define MROWS  (NBATCH * NNODES)   // 32768
#define FMAX   512

// ---------------- scratch (device globals; no allocation allowed) ----------
__device__ float g_h[MROWS * FMAX];      // GEMM output per layer (sel 0)
__device__ float g_bufA[MROWS * FMAX];   // ping (sel 1)
__device__ float g_bufB[MROWS * FMAX];   // pong (sel 2)
__device__ float g_inv_sqrt_deg[NNODES];
__device__ float g_inv_deg[NNODES];
__device__ int   g_cnt[NNODES];
__device__ int   g_off[NNODES + 1];
__device__ int   g_cur[NNODES];
__device__ int   g_csr_edge[NEDGES];
__device__ int   g_csr_src[NEDGES];
__device__ float g_csr_norm[NEDGES];
__device__ int   g_e64;                  // 1 if edges stored as int64, 0 if int32

__device__ __forceinline__ float* buf_ptr(int s) {
    return (s == 0) ? g_h : (s == 1) ? g_bufA : g_bufB;
}

// read edge element i (flat index into the (2,E) array) under either dtype
__device__ __forceinline__ int edge_at(const void* edges, int i) {
    if (g_e64) {
        long long v = ((const long long*)edges)[i];
        return (int)v;
    }
    return ((const int*)edges)[i];
}

// ---------------- edge dtype detection -------------------------------------
// Safe under both dtypes: reads only the first 24576 32-bit words (the int32
// buffer is exactly that size; the int64 buffer is twice that). If edges are
// little-endian int64 with values in [0,2048), every odd word is 0. A genuine
// int32 edge array would need 12288 random values to all be 0 — impossible.
__global__ void k_detect_dtype(const void* edges) {
    __shared__ int any_nz;
    if (threadIdx.x == 0) any_nz = 0;
    __syncthreads();
    const int* w = (const int*)edges;
    int local = 0;
    for (int i = threadIdx.x; i < 2 * NEDGES / 2; i += blockDim.x)
        local |= w[2 * i + 1];
    if (local) atomicOr(&any_nz, 1);
    __syncthreads();
    if (threadIdx.x == 0) g_e64 = any_nz ? 0 : 1;
}

// ---------------- graph preprocessing --------------------------------------
__global__ void k_zero_cnt() {
    int i = blockIdx.x * blockDim.x + threadIdx.x;
    if (i < NNODES) g_cnt[i] = 0;
}

__global__ void k_count(const void* edges) {
    int e = blockIdx.x * blockDim.x + threadIdx.x;
    if (e < NEDGES) {
        int dst = edge_at(edges, NEDGES + e);
        if (dst >= 0 && dst < NNODES) atomicAdd(&g_cnt[dst], 1);
    }
}

// one block, 256 threads: exclusive scan of g_cnt into g_off / g_cur
__global__ void k_scan() {
    __shared__ int sc[NNODES];
    __shared__ int part[256];
    int t = threadIdx.x;
    for (int i = t; i < NNODES; i += 256) sc[i] = g_cnt[i];
    __syncthreads();
    int base = t * 8;
    int s = 0;
#pragma unroll
    for (int i = 0; i < 8; i++) s += sc[base + i];
    part[t] = s;
    __syncthreads();
    if (t == 0) {
        int a = 0;
        for (int i = 0; i < 256; i++) { int v = part[i]; part[i] = a; a += v; }
        g_off[NNODES] = a;
    }
    __syncthreads();
    int a = part[t];
#pragma unroll
    for (int i = 0; i < 8; i++) {
        int v = sc[base + i];
        g_off[base + i] = a;
        g_cur[base + i] = a;
        a += v;
    }
}

__global__ void k_deg_finish() {
    int n = blockIdx.x * blockDim.x + threadIdx.x;
    if (n < NNODES) {
        float d = (float)g_cnt[n] + 1.0f;
        g_inv_sqrt_deg[n] = rsqrtf(d);
        g_inv_deg[n] = 1.0f / d;
    }
}

__global__ void k_scatter(const void* edges) {
    int e = blockIdx.x * blockDim.x + threadIdx.x;
    if (e < NEDGES) {
        int dst = edge_at(edges, NEDGES + e);
        if (dst >= 0 && dst < NNODES) {
            int p = atomicAdd(&g_cur[dst], 1);
            if (p >= 0 && p < NEDGES) g_csr_edge[p] = e;
        }
    }
}

// sort each bucket by edge id (determinism) and precompute src + norm
__global__ void k_sort_fill(const void* edges) {
    int n = blockIdx.x * blockDim.x + threadIdx.x;
    if (n >= NNODES) return;
    int s = g_off[n], e = g_off[n + 1];
    for (int i = s + 1; i < e; i++) {
        int v = g_csr_edge[i];
        int j = i - 1;
        while (j >= s && g_csr_edge[j] > v) { g_csr_edge[j + 1] = g_csr_edge[j]; j--; }
        g_csr_edge[j + 1] = v;
    }
    float isd_n = g_inv_sqrt_deg[n];
    for (int i = s; i < e; i++) {
        int eid = g_csr_edge[i];
        int src = edge_at(edges, eid);
        if (src < 0) src = 0;
        if (src >= NNODES) src = NNODES - 1;
        g_csr_src[i] = src;
        g_csr_norm[i] = isd_n * g_inv_sqrt_deg[src];
    }
}

// ---------------- tiled fp32 SGEMM: C[M,N] = A[M,K] * W[K,N] ----------------
// BM=128, BN=128, BK=16, 256 threads, 8x8 microtile.
__global__ __launch_bounds__(256, 2)
void k_sgemm(const float* __restrict__ Aext, int Asel, const float* __restrict__ W,
             int Csel, int M, int K, int Ncols) {
    const float* A = (Asel < 0) ? Aext : buf_ptr(Asel);
    float* C = buf_ptr(Csel);

    __shared__ float As[16][132];
    __shared__ float Bs[16][132];

    int tid = threadIdx.x;
    int tx = tid & 15;
    int ty = tid >> 4;
    int rowBase = blockIdx.y * 128;
    int colBase = blockIdx.x * 128;

    float acc[8][8];
#pragma unroll
    for (int i = 0; i < 8; i++)
#pragma unroll
        for (int j = 0; j < 8; j++) acc[i][j] = 0.0f;

    for (int k0 = 0; k0 < K; k0 += 16) {
        // A tile: 128 rows x 16 k, scalar loads (handles K=1475 misalignment)
#pragma unroll
        for (int p = 0; p < 8; p++) {
            int lin = tid + p * 256;
            int r = lin >> 4;
            int kk = lin & 15;
            int gk = k0 + kk;
            float v = 0.0f;
            if (gk < K) v = A[(size_t)(rowBase + r) * K + gk];
            As[kk][r] = v;
        }
        // W tile: 16 k x 128 cols, float4 (Ncols % 4 == 0 always here)
#pragma unroll
        for (int p = 0; p < 2; p++) {
            int idx = tid + p * 256;
            int kk = idx >> 5;
            int c4 = (idx & 31) * 4;
            int gk = k0 + kk;
            int gc = colBase + c4;
            float4 v = make_float4(0.f, 0.f, 0.f, 0.f);
            if (gk < K && gc + 3 < Ncols)
                v = *reinterpret_cast<const float4*>(W + (size_t)gk * Ncols + gc);
            *reinterpret_cast<float4*>(&Bs[kk][c4]) = v;
        }
        __syncthreads();

#pragma unroll
        for (int k = 0; k < 16; k++) {
            float4 a0 = *reinterpret_cast<const float4*>(&As[k][ty * 8]);
            float4 a1 = *reinterpret_cast<const float4*>(&As[k][ty * 8 + 4]);
            float4 b0 = *reinterpret_cast<const float4*>(&Bs[k][tx * 8]);
            float4 b1 = *reinterpret_cast<const float4*>(&Bs[k][tx * 8 + 4]);
            float ar[8] = {a0.x, a0.y, a0.z, a0.w, a1.x, a1.y, a1.z, a1.w};
            float br[8] = {b0.x, b0.y, b0.z, b0.w, b1.x, b1.y, b1.z, b1.w};
#pragma unroll
            for (int i = 0; i < 8; i++)
#pragma unroll
                for (int j = 0; j < 8; j++)
                    acc[i][j] = fmaf(ar[i], br[j], acc[i][j]);
        }
        __syncthreads();
    }

#pragma unroll
    for (int i = 0; i < 8; i++) {
        int gr = rowBase + ty * 8 + i;
#pragma unroll
        for (int j = 0; j < 8; j++) {
            int gc = colBase + tx * 8 + j;
            if (gc < Ncols) C[(size_t)gr * Ncols + gc] = acc[i][j];
        }
    }
}

// ---------------- layer 5 GEMM: [32768,64] x [64,3] -------------------------
__global__ void k_gemm_n3(int Asel, const float* __restrict__ W5, int Csel) {
    const float* A = buf_ptr(Asel);
    float* Hout = buf_ptr(Csel);
    __shared__ float ws[64 * 3];
    int tid = threadIdx.x;
    if (tid < 192) ws[tid] = W5[tid];
    __syncthreads();
    int warp = tid >> 5, lane = tid & 31;
    int row = blockIdx.x * 8 + warp;
    const float* ar = A + (size_t)row * 64;
    float a0 = ar[lane];
    float a1 = ar[lane + 32];
#pragma unroll
    for (int c = 0; c < 3; c++) {
        float v = a0 * ws[lane * 3 + c] + a1 * ws[(lane + 32) * 3 + c];
#pragma unroll
        for (int o = 16; o > 0; o >>= 1) v += __shfl_down_sync(0xffffffffu, v, o);
        if (lane == 0) Hout[(size_t)row * 3 + c] = v;
    }
}

// ---------------- GCN aggregation (gather, no atomics) ----------------------
__global__ void k_agg(int Hsel, const float* __restrict__ bias,
                      int Osel, int F, int leaky) {
    const float* H = buf_ptr(Hsel);
    float* Out = buf_ptr(Osel);
    int idx = blockIdx.x * blockDim.x + threadIdx.x;
    int total = NBATCH * NNODES * F;
    if (idx >= total) return;
    int f = idx % F;
    int bn = idx / F;
    int n = bn & (NNODES - 1);
    int b = bn >> 11;
    const float* Hb = H + (size_t)b * NNODES * F;
    float acc = Hb[(size_t)n * F + f] * g_inv_deg[n] + bias[f];
    int s = g_off[n], e = g_off[n + 1];
    for (int j = s; j < e; j++)
        acc += Hb[(size_t)g_csr_src[j] * F + f] * g_csr_norm[j];
    if (leaky && acc < 0.0f) acc *= 0.01f;
    Out[idx] = acc;
}

// ---------------- dense head: tanh(feat[16,6144] @ Wd + bd) * 0.1 -----------
__global__ void k_dense(int Fsel, const float* __restrict__ Wd,
                        const float* __restrict__ bd, float* __restrict__ out) {
    const float* feat = buf_ptr(Fsel);
    __shared__ float fs[16][128];
    int col = blockIdx.x * 128 + threadIdx.x;
    float acc[16];
#pragma unroll
    for (int b = 0; b < 16; b++) acc[b] = 0.0f;

    for (int k0 = 0; k0 < DDENSE; k0 += 128) {
#pragma unroll
        for (int p = 0; p < 16; p++) {
            int lin = threadIdx.x + p * 128;
            int bb = lin >> 7, kk = lin & 127;
            fs[bb][kk] = feat[(size_t)bb * DDENSE + k0 + kk];
        }
        __syncthreads();
#pragma unroll 4
        for (int k = 0; k < 128; k++) {
            float w = Wd[(size_t)(k0 + k) * DDENSE + col];
#pragma unroll
            for (int b = 0; b < 16; b++) acc[b] = fmaf(fs[b][k], w, acc[b]);
        }
        __syncthreads();
    }
    float bias = bd[col];
#pragma unroll
    for (int b = 0; b < 16; b++)
        out[(size_t)b * DDENSE + col] = tanhf(acc[b] + bias) * 0.1f;
}

// ---------------- launch ----------------------------------------------------
extern "C" void kernel_launch(void* const* d_in, const int* in_sizes, int n_in,
                              void* d_out, int out_size) {
    // Identify inputs by element count (robust to metadata ordering).
    const float* x = nullptr; const void* edges = nullptr;
    const float* W[6] = {0}; const float* bb[6] = {0};
    const float* Wd = nullptr; const float* bd = nullptr;
    int n512 = 0, n256 = 0;
    for (int i = 0; i < n_in; i++) {
        const void* p = d_in[i];
        switch (in_sizes[i]) {
            case 48332800: x = (const float*)p; break;            // 16*2048*1475
            case 24576:    edges = p; break;                      // 2*12288
            case 755200:   W[0] = (const float*)p; break;         // 1475*512
            case 262144:   W[1] = (const float*)p; break;         // 512*512
            case 131072:   W[2] = (const float*)p; break;         // 512*256
            case 65536:    W[3] = (const float*)p; break;         // 256*256
            case 16384:    W[4] = (const float*)p; break;         // 256*64
            case 192:      W[5] = (const float*)p; break;         // 64*3
            case 37748736: Wd = (const float*)p; break;           // 6144*6144
            case 6144:     bd = (const float*)p; break;
            case 512:      bb[n512 == 0 ? 0 : 1] = (const float*)p; n512++; break;
            case 256:      bb[n256 == 0 ? 2 : 3] = (const float*)p; n256++; break;
            case 64:       bb[4] = (const float*)p; break;
            case 3:        bb[5] = (const float*)p; break;
            default: break;
        }
    }
    float* out = (float*)d_out;

    // graph preprocessing
    k_detect_dtype<<<1, 256>>>(edges);
    k_zero_cnt<<<(NNODES + 255) / 256, 256>>>();
    k_count<<<(NEDGES + 255) / 256, 256>>>(edges);
    k_scan<<<1, 256>>>();
    k_deg_finish<<<(NNODES + 255) / 256, 256>>>();
    k_scatter<<<(NEDGES + 255) / 256, 256>>>(edges);
    k_sort_fill<<<(NNODES + 255) / 256, 256>>>(edges);

    const int aggT = 256;
    // layer 0: [32768,1475]x[1475,512]   (A = external x)
    k_sgemm<<<dim3(4, 256), 256>>>(x, -1, W[0], 0, MROWS, 1475, 512);
    k_agg<<<(MROWS * 512 + aggT - 1) / aggT, aggT>>>(0, bb[0], 1, 512, 0);
    // layer 1: 512x512, LeakyReLU
    k_sgemm<<<dim3(4, 256), 256>>>(nullptr, 1, W[1], 0, MROWS, 512, 512);
    k_agg<<<(MROWS * 512 + aggT - 1) / aggT, aggT>>>(0, bb[1], 2, 512, 1);
    // layer 2: 512x256
    k_sgemm<<<dim3(2, 256), 256>>>(nullptr, 2, W[2], 0, MROWS, 512, 256);
    k_agg<<<(MROWS * 256 + aggT - 1) / aggT, aggT>>>(0, bb[2], 1, 256, 0);
    // layer 3: 256x256, LeakyReLU
    k_sgemm<<<dim3(2, 256), 256>>>(nullptr, 1, W[3], 0, MROWS, 256, 256);
    k_agg<<<(MROWS * 256 + aggT - 1) / aggT, aggT>>>(0, bb[3], 2, 256, 1);
    // layer 4: 256x64
    k_sgemm<<<dim3(1, 256), 256>>>(nullptr, 2, W[4], 0, MROWS, 256, 64);
    k_agg<<<(MROWS * 64 + aggT - 1) / aggT, aggT>>>(0, bb[4], 1, 64, 0);
    // layer 5: 64x3, LeakyReLU
    k_gemm_n3<<<MROWS / 8, 256>>>(1, W[5], 0);
    k_agg<<<(MROWS * 3 + aggT - 1) / aggT, aggT>>>(0, bb[5], 2, 3, 1);
    // dense head
    k_dense<<<DDENSE / 128, 128>>>(2, Wd, bd, out);
}

// round 9
// speedup vs baseline: 1.0060x; 1.0060x over previous
#include <cuda_runtime.h>
#include <cuda_bf16.h>
#include <math.h>
#include <stdint.h>

#define NNODES 2048
#define NBATCH 16
#define NEDGES 12288
#define DDENSE 6144
#define MROWS  (NBATCH * NNODES)   // 32768
#define FMAX   512
#define CHMAX  93                  // ceil(1475/16)

// ---------------- scratch (device globals; no allocation allowed) ----------
__device__ float g_h[MROWS * FMAX];      // GEMM output per layer (sel 0)
__device__ float g_bufA[MROWS * FMAX];   // ping (sel 1)
__device__ float g_bufB[MROWS * FMAX];   // pong (sel 2)
__device__ __nv_bfloat16 g_abf[(size_t)MROWS * CHMAX * 64];  // bf16x3 A operand
__device__ __nv_bfloat16 g_wbf[(size_t)512 * CHMAX * 64];    // bf16x3 W operand
__device__ float g_inv_sqrt_deg[NNODES];
__device__ float g_inv_deg[NNODES];
__device__ int   g_cnt[NNODES];
__device__ int   g_off[NNODES + 1];
__device__ int   g_cur[NNODES];
__device__ int   g_csr_edge[NEDGES];
__device__ int   g_csr_src[NEDGES];
__device__ float g_csr_norm[NEDGES];
__device__ int   g_e64;

__device__ __forceinline__ float* buf_ptr(int s) {
    return (s == 0) ? g_h : (s == 1) ? g_bufA : g_bufB;
}

// ---------------- base-ISA helpers ------------------------------------------
__device__ __forceinline__ uint32_t smem_u32(const void* p) {
    uint32_t a;
    asm("{ .reg .u64 t; cvta.to.shared.u64 t, %1; cvt.u32.u64 %0, t; }" : "=r"(a) : "l"(p));
    return a;
}
#define SWZ(o) ((o) ^ (((o) >> 3) & 0x70))
__device__ __forceinline__ void cp16(uint32_t saddr, const void* g) {
    asm volatile("cp.async.cg.shared.global [%0], [%1], 16;" :: "r"(saddr), "l"(g));
}
#define CP_COMMIT() asm volatile("cp.async.commit_group;" ::: "memory")
#define CP_WAIT1()  asm volatile("cp.async.wait_group 1;" ::: "memory")
#define CP_WAIT0()  asm volatile("cp.async.wait_group 0;" ::: "memory")
__device__ __forceinline__ void ldm_x4(uint32_t& r0, uint32_t& r1, uint32_t& r2, uint32_t& r3,
                                       uint32_t addr) {
    asm volatile("ldmatrix.sync.aligned.m8n8.x4.shared.b16 {%0,%1,%2,%3}, [%4];"
                 : "=r"(r0), "=r"(r1), "=r"(r2), "=r"(r3) : "r"(addr));
}
__device__ __forceinline__ void mma_bf16(float& c0, float& c1, float& c2, float& c3,
                                         uint32_t a0, uint32_t a1, uint32_t a2, uint32_t a3,
                                         uint32_t b0, uint32_t b1) {
    asm volatile(
        "mma.sync.aligned.m16n8k16.row.col.f32.bf16.bf16.f32 "
        "{%0,%1,%2,%3}, {%4,%5,%6,%7}, {%8,%9}, {%0,%1,%2,%3};"
        : "+f"(c0), "+f"(c1), "+f"(c2), "+f"(c3)
        : "r"(a0), "r"(a1), "r"(a2), "r"(a3), "r"(b0), "r"(b1));
}

// ---------------- edge helpers ----------------------------------------------
__device__ __forceinline__ int edge_at(const void* edges, int i) {
    if (g_e64) return (int)((const long long*)edges)[i];
    return ((const int*)edges)[i];
}

__global__ void k_detect_dtype(const void* edges) {
    __shared__ int any_nz;
    if (threadIdx.x == 0) any_nz = 0;
    __syncthreads();
    const int* w = (const int*)edges;
    int local = 0;
    for (int i = threadIdx.x; i < NEDGES; i += blockDim.x) local |= w[2 * i + 1];
    if (local) atomicOr(&any_nz, 1);
    __syncthreads();
    if (threadIdx.x == 0) g_e64 = any_nz ? 0 : 1;
}

// ---------------- graph preprocessing ----------------------------------------
__global__ void k_zero_cnt() {
    int i = blockIdx.x * blockDim.x + threadIdx.x;
    if (i < NNODES) g_cnt[i] = 0;
}
__global__ void k_count(const void* edges) {
    int e = blockIdx.x * blockDim.x + threadIdx.x;
    if (e < NEDGES) {
        int dst = edge_at(edges, NEDGES + e);
        if (dst >= 0 && dst < NNODES) atomicAdd(&g_cnt[dst], 1);
    }
}
__global__ void k_scan() {
    __shared__ int sc[NNODES];
    __shared__ int part[256];
    int t = threadIdx.x;
    for (int i = t; i < NNODES; i += 256) sc[i] = g_cnt[i];
    __syncthreads();
    int base = t * 8, s = 0;
#pragma unroll
    for (int i = 0; i < 8; i++) s += sc[base + i];
    part[t] = s;
    __syncthreads();
    if (t == 0) {
        int a = 0;
        for (int i = 0; i < 256; i++) { int v = part[i]; part[i] = a; a += v; }
        g_off[NNODES] = a;
    }
    __syncthreads();
    int a = part[t];
#pragma unroll
    for (int i = 0; i < 8; i++) {
        int v = sc[base + i];
        g_off[base + i] = a;
        g_cur[base + i] = a;
        a += v;
    }
}
__global__ void k_deg_finish() {
    int n = blockIdx.x * blockDim.x + threadIdx.x;
    if (n < NNODES) {
        float d = (float)g_cnt[n] + 1.0f;
        g_inv_sqrt_deg[n] = rsqrtf(d);
        g_inv_deg[n] = 1.0f / d;
    }
}
__global__ void k_scatter(const void* edges) {
    int e = blockIdx.x * blockDim.x + threadIdx.x;
    if (e < NEDGES) {
        int dst = edge_at(edges, NEDGES + e);
        if (dst >= 0 && dst < NNODES) {
            int p = atomicAdd(&g_cur[dst], 1);
            if (p >= 0 && p < NEDGES) g_csr_edge[p] = e;
        }
    }
}
__global__ void k_sort_fill(const void* edges) {
    int n = blockIdx.x * blockDim.x + threadIdx.x;
    if (n >= NNODES) return;
    int s = g_off[n], e = g_off[n + 1];
    for (int i = s + 1; i < e; i++) {
        int v = g_csr_edge[i];
        int j = i - 1;
        while (j >= s && g_csr_edge[j] > v) { g_csr_edge[j + 1] = g_csr_edge[j]; j--; }
        g_csr_edge[j + 1] = v;
    }
    float isd_n = g_inv_sqrt_deg[n];
    for (int i = s; i < e; i++) {
        int src = edge_at(edges, g_csr_edge[i]);
        if (src < 0) src = 0;
        if (src >= NNODES) src = NNODES - 1;
        g_csr_src[i] = src;
        g_csr_norm[i] = isd_n * g_inv_sqrt_deg[src];
    }
}

// ---------------- bf16x3 conversion -----------------------------------------
// A' layout: [m][c][slot<64>], slot = g*16+t; g in {0,1}: hi, g in {2,3}: lo
__global__ void k_convA(const float* __restrict__ Aext, int Asel, int K, int CH) {
    const float* A = (Asel < 0) ? Aext : buf_ptr(Asel);
    size_t idx = (size_t)blockIdx.x * 256 + threadIdx.x;
    size_t total = (size_t)MROWS * CH * 64;
    if (idx >= total) return;
    int slot = (int)(idx & 63);
    size_t rest = idx >> 6;
    int c = (int)(rest % CH);
    int m = (int)(rest / CH);
    int g = slot >> 4, t = slot & 15;
    int k = c * 16 + t;
    float v = (k < K) ? A[(size_t)m * K + k] : 0.0f;
    __nv_bfloat16 hi = __float2bfloat16(v);
    __nv_bfloat16 o = (g < 2) ? hi : __float2bfloat16(v - __bfloat162float(hi));
    g_abf[idx] = o;
}
// W' layout: [n][c][slot]; g==1: lo, else hi
__global__ void k_convW(const float* __restrict__ W, int N, int K, int CH) {
    int idx = blockIdx.x * 256 + threadIdx.x;
    int total = N * CH * 64;
    if (idx >= total) return;
    int slot = idx & 63;
    int rest = idx >> 6;
    int c = rest % CH;
    int n = rest / CH;
    int g = slot >> 4, t = slot & 15;
    int k = c * 16 + t;
    float v = (k < K) ? W[(size_t)k * N + n] : 0.0f;
    __nv_bfloat16 hi = __float2bfloat16(v);
    __nv_bfloat16 o = (g == 1) ? __float2bfloat16(v - __bfloat162float(hi)) : hi;
    g_wbf[idx] = o;
}

// ---------------- mma.sync bf16x3 GEMM: C[M,N] = A' @ W'^T -------------------
// 128x128 block, 256 threads, warp tile 64x32 (2x4 warps).
// Per chunk c: SMEM A 128x64 bf16, B 128x64 bf16 (both SW-swizzled),
// 3 k16 MMA groups (g=0,1,2; g=3 unused duplicate).
#define MMG_SMEM 65536   // 2 stages x (16K A + 16K B)
__global__ void __launch_bounds__(256)
k_mmagemm(int Csel, int CH, int Nlayer) {
    extern __shared__ char dsm[];
    float* C = buf_ptr(Csel);
    const int tid = threadIdx.x, wid = tid >> 5, lane = tid & 31;
    const int wy = wid >> 2, wx = wid & 3;           // warp tile origin
    const int rowBase = blockIdx.y * 128;
    const int colBase = blockIdx.x * 128;
    const size_t arow = (size_t)CH * 64;
    const uint32_t sb = smem_u32(dsm);

    float acc[4][4][4];
#pragma unroll
    for (int i = 0; i < 4; i++)
#pragma unroll
        for (int j = 0; j < 4; j++)
#pragma unroll
            for (int q = 0; q < 4; q++) acc[i][j][q] = 0.0f;

    // prefetch chunk 0 into stage 0
    {
        uint32_t As = sb, Bs = sb + 16384;
#pragma unroll
        for (int p = 0; p < 8; p++) {
            int v = tid + p * 256;
            if (v < 1024) {
                int r = v >> 3, seg = v & 7;
                cp16(As + SWZ(r * 128 + seg * 16),
                     g_abf + (size_t)(rowBase + r) * arow + seg * 8);
            } else {
                int v2 = v - 1024;
                int r = v2 >> 3, seg = v2 & 7;
                cp16(Bs + SWZ(r * 128 + seg * 16),
                     g_wbf + (size_t)(colBase + r) * arow + seg * 8);
            }
        }
        CP_COMMIT();
    }

    for (int c = 0; c < CH; c++) {
        if (c + 1 < CH) {
            uint32_t stg = sb + ((c + 1) & 1) * 32768;
            uint32_t As = stg, Bs = stg + 16384;
            size_t coff = (size_t)(c + 1) * 64;
#pragma unroll
            for (int p = 0; p < 8; p++) {
                int v = tid + p * 256;
                if (v < 1024) {
                    int r = v >> 3, seg = v & 7;
                    cp16(As + SWZ(r * 128 + seg * 16),
                         g_abf + (size_t)(rowBase + r) * arow + coff + seg * 8);
                } else {
                    int v2 = v - 1024;
                    int r = v2 >> 3, seg = v2 & 7;
                    cp16(Bs + SWZ(r * 128 + seg * 16),
                         g_wbf + (size_t)(colBase + r) * arow + coff + seg * 8);
                }
            }
            CP_COMMIT();
            CP_WAIT1();
        } else {
            CP_WAIT0();
        }
        __syncthreads();

        uint32_t stg = sb + (c & 1) * 32768;
        uint32_t As = stg, Bs = stg + 16384;
#pragma unroll
        for (int g = 0; g < 3; g++) {
            uint32_t a[4][4], b[4][2];
#pragma unroll
            for (int mt = 0; mt < 4; mt++) {
                int row = wy * 64 + mt * 16 + (lane & 15);
                int bo = g * 32 + ((lane >> 4) << 4);
                ldm_x4(a[mt][0], a[mt][1], a[mt][2], a[mt][3], As + SWZ(row * 128 + bo));
            }
#pragma unroll
            for (int jp = 0; jp < 2; jp++) {
                int nrow = wx * 32 + jp * 16 + (lane & 7) + ((lane >> 4) << 3);
                int bo = g * 32 + (((lane >> 3) & 1) << 4);
                ldm_x4(b[jp * 2][0], b[jp * 2][1], b[jp * 2 + 1][0], b[jp * 2 + 1][1],
                       Bs + SWZ(nrow * 128 + bo));
            }
#pragma unroll
            for (int mt = 0; mt < 4; mt++)
#pragma unroll
                for (int nt = 0; nt < 4; nt++)
                    mma_bf16(acc[mt][nt][0], acc[mt][nt][1], acc[mt][nt][2], acc[mt][nt][3],
                             a[mt][0], a[mt][1], a[mt][2], a[mt][3],
                             b[nt][0], b[nt][1]);
        }
        __syncthreads();
    }

    // epilogue: fragment c layout -> C
#pragma unroll
    for (int mt = 0; mt < 4; mt++) {
        int r0 = rowBase + wy * 64 + mt * 16 + (lane >> 2);
#pragma unroll
        for (int nt = 0; nt < 4; nt++) {
            int col = colBase + wx * 32 + nt * 8 + (lane & 3) * 2;
            float2 v0 = make_float2(acc[mt][nt][0], acc[mt][nt][1]);
            float2 v1 = make_float2(acc[mt][nt][2], acc[mt][nt][3]);
            *reinterpret_cast<float2*>(C + (size_t)r0 * Nlayer + col) = v0;
            *reinterpret_cast<float2*>(C + (size_t)(r0 + 8) * Nlayer + col) = v1;
        }
    }
}

// ---------------- fp32 SGEMM (layer 4: K=256, N=64) --------------------------
__global__ __launch_bounds__(256, 2)
void k_sgemm(int Asel, const float* __restrict__ W,
             int Csel, int M, int K, int Ncols) {
    const float* A = buf_ptr(Asel);
    float* C = buf_ptr(Csel);
    __shared__ float As[16][132];
    __shared__ float Bs[16][132];
    int tid = threadIdx.x;
    int tx = tid & 15, ty = tid >> 4;
    int rowBase = blockIdx.y * 128;
    int colBase = blockIdx.x * 128;
    float acc[8][8];
#pragma unroll
    for (int i = 0; i < 8; i++)
#pragma unroll
        for (int j = 0; j < 8; j++) acc[i][j] = 0.0f;
    for (int k0 = 0; k0 < K; k0 += 16) {
#pragma unroll
        for (int p = 0; p < 8; p++) {
            int lin = tid + p * 256;
            int r = lin >> 4, kk = lin & 15;
            int gk = k0 + kk;
            float v = (gk < K) ? A[(size_t)(rowBase + r) * K + gk] : 0.0f;
            As[kk][r] = v;
        }
#pragma unroll
        for (int p = 0; p < 2; p++) {
            int idx = tid + p * 256;
            int kk = idx >> 5, c4 = (idx & 31) * 4;
            int gk = k0 + kk, gc = colBase + c4;
            float4 v = make_float4(0.f, 0.f, 0.f, 0.f);
            if (gk < K && gc + 3 < Ncols)
                v = *reinterpret_cast<const float4*>(W + (size_t)gk * Ncols + gc);
            *reinterpret_cast<float4*>(&Bs[kk][c4]) = v;
        }
        __syncthreads();
#pragma unroll
        for (int k = 0; k < 16; k++) {
            float4 a0 = *reinterpret_cast<const float4*>(&As[k][ty * 8]);
            float4 a1 = *reinterpret_cast<const float4*>(&As[k][ty * 8 + 4]);
            float4 b0 = *reinterpret_cast<const float4*>(&Bs[k][tx * 8]);
            float4 b1 = *reinterpret_cast<const float4*>(&Bs[k][tx * 8 + 4]);
            float ar[8] = {a0.x, a0.y, a0.z, a0.w, a1.x, a1.y, a1.z, a1.w};
            float br[8] = {b0.x, b0.y, b0.z, b0.w, b1.x, b1.y, b1.z, b1.w};
#pragma unroll
            for (int i = 0; i < 8; i++)
#pragma unroll
                for (int j = 0; j < 8; j++)
                    acc[i][j] = fmaf(ar[i], br[j], acc[i][j]);
        }
        __syncthreads();
    }
#pragma unroll
    for (int i = 0; i < 8; i++) {
        int gr = rowBase + ty * 8 + i;
#pragma unroll
        for (int j = 0; j < 8; j++) {
            int gc = colBase + tx * 8 + j;
            if (gc < Ncols) C[(size_t)gr * Ncols + gc] = acc[i][j];
        }
    }
}

// ---------------- layer 5 GEMM: [32768,64] x [64,3] --------------------------
__global__ void k_gemm_n3(int Asel, const float* __restrict__ W5, int Csel) {
    const float* A = buf_ptr(Asel);
    float* Hout = buf_ptr(Csel);
    __shared__ float ws[64 * 3];
    int tid = threadIdx.x;
    if (tid < 192) ws[tid] = W5[tid];
    __syncthreads();
    int warp = tid >> 5, lane = tid & 31;
    int row = blockIdx.x * 8 + warp;
    const float* ar = A + (size_t)row * 64;
    float a0 = ar[lane];
    float a1 = ar[lane + 32];
#pragma unroll
    for (int c = 0; c < 3; c++) {
        float v = a0 * ws[lane * 3 + c] + a1 * ws[(lane + 32) * 3 + c];
#pragma unroll
        for (int o = 16; o > 0; o >>= 1) v += __shfl_down_sync(0xffffffffu, v, o);
        if (lane == 0) Hout[(size_t)row * 3 + c] = v;
    }
}

// ---------------- GCN aggregation (gather) -----------------------------------
__global__ void k_agg(int Hsel, const float* __restrict__ bias,
                      int Osel, int F, int leaky) {
    const float* H = buf_ptr(Hsel);
    float* Out = buf_ptr(Osel);
    int idx = blockIdx.x * blockDim.x + threadIdx.x;
    int total = NBATCH * NNODES * F;
    if (idx >= total) return;
    int f = idx % F;
    int bn = idx / F;
    int n = bn & (NNODES - 1);
    int b = bn >> 11;
    const float* Hb = H + (size_t)b * NNODES * F;
    float acc = Hb[(size_t)n * F + f] * g_inv_deg[n] + bias[f];
    int s = g_off[n], e = g_off[n + 1];
    for (int j = s; j < e; j++)
        acc += Hb[(size_t)g_csr_src[j] * F + f] * g_csr_norm[j];
    if (leaky && acc < 0.0f) acc *= 0.01f;
    Out[idx] = acc;
}

// ---------------- dense head -------------------------------------------------
__global__ void k_dense(int Fsel, const float* __restrict__ Wd,
                        const float* __restrict__ bd, float* __restrict__ out) {
    const float* feat = buf_ptr(Fsel);
    __shared__ float fs[16][128];
    int col = blockIdx.x * 128 + threadIdx.x;
    float acc[16];
#pragma unroll
    for (int b = 0; b < 16; b++) acc[b] = 0.0f;
    for (int k0 = 0; k0 < DDENSE; k0 += 128) {
#pragma unroll
        for (int p = 0; p < 16; p++) {
            int lin = threadIdx.x + p * 128;
            fs[lin >> 7][lin & 127] = feat[(size_t)(lin >> 7) * DDENSE + k0 + (lin & 127)];
        }
        __syncthreads();
#pragma unroll 4
        for (int k = 0; k < 128; k++) {
            float w = Wd[(size_t)(k0 + k) * DDENSE + col];
#pragma unroll
            for (int b = 0; b < 16; b++) acc[b] = fmaf(fs[b][k], w, acc[b]);
        }
        __syncthreads();
    }
    float bias = bd[col];
#pragma unroll
    for (int b = 0; b < 16; b++)
        out[(size_t)b * DDENSE + col] = tanhf(acc[b] + bias) * 0.1f;
}

// ---------------- launch -----------------------------------------------------
extern "C" void kernel_launch(void* const* d_in, const int* in_sizes, int n_in,
                              void* d_out, int out_size) {
    const float* x = nullptr; const void* edges = nullptr;
    const float* W[6] = {0}; const float* bb[6] = {0};
    const float* Wd = nullptr; const float* bd = nullptr;
    int n512 = 0, n256 = 0;
    for (int i = 0; i < n_in; i++) {
        const void* p = d_in[i];
        switch (in_sizes[i]) {
            case 48332800: x = (const float*)p; break;
            case 24576:    edges = p; break;
            case 755200:   W[0] = (const float*)p; break;
            case 262144:   W[1] = (const float*)p; break;
            case 131072:   W[2] = (const float*)p; break;
            case 65536:    W[3] = (const float*)p; break;
            case 16384:    W[4] = (const float*)p; break;
            case 192:      W[5] = (const float*)p; break;
            case 37748736: Wd = (const float*)p; break;
            case 6144:     bd = (const float*)p; break;
            case 512:      bb[n512 == 0 ? 0 : 1] = (const float*)p; n512++; break;
            case 256:      bb[n256 == 0 ? 2 : 3] = (const float*)p; n256++; break;
            case 64:       bb[4] = (const float*)p; break;
            case 3:        bb[5] = (const float*)p; break;
            default: break;
        }
    }
    float* out = (float*)d_out;

    cudaFuncSetAttribute(k_mmagemm, cudaFuncAttributeMaxDynamicSharedMemorySize, MMG_SMEM);

    // graph preprocessing
    k_detect_dtype<<<1, 256>>>(edges);
    k_zero_cnt<<<(NNODES + 255) / 256, 256>>>();
    k_count<<<(NEDGES + 255) / 256, 256>>>(edges);
    k_scan<<<1, 256>>>();
    k_deg_finish<<<(NNODES + 255) / 256, 256>>>();
    k_scatter<<<(NEDGES + 255) / 256, 256>>>(edges);
    k_sort_fill<<<(NNODES + 255) / 256, 256>>>(edges);

    const int aggT = 256;
    // layers 0-3 on tensor cores (bf16x3)
    struct { int K, N, inSel, outSel, leaky; } L[4] = {
        {1475, 512, -1, 1, 0},
        { 512, 512,  1, 2, 1},
        { 512, 256,  2, 1, 0},
        { 256, 256,  1, 2, 1},
    };
    for (int i = 0; i < 4; i++) {
        int K = L[i].K, N = L[i].N;
        int CH = (K + 15) / 16;
        size_t totA = (size_t)MROWS * CH * 64;
        int totW = N * CH * 64;
        k_convA<<<(unsigned)((totA + 255) / 256), 256>>>(x, L[i].inSel, K, CH);
        k_convW<<<(totW + 255) / 256, 256>>>(W[i], N, K, CH);
        dim3 grid(N / 128, MROWS / 128);
        k_mmagemm<<<grid, 256, MMG_SMEM>>>(0, CH, N);
        k_agg<<<(MROWS * N + aggT - 1) / aggT, aggT>>>(0, bb[i], L[i].outSel, N, L[i].leaky);
    }
    // layer 4: fp32 SGEMM [32768,256]x[256,64]
    k_sgemm<<<dim3(1, 256), 256>>>(2, W[4], 0, MROWS, 256, 64);
    k_agg<<<(MROWS * 64 + aggT - 1) / aggT, aggT>>>(0, bb[4], 1, 64, 0);
    // layer 5: 64x3 + agg(leaky)
    k_gemm_n3<<<MROWS / 8, 256>>>(1, W[5], 0);
    k_agg<<<(MROWS * 3 + aggT - 1) / aggT, aggT>>>(0, bb[5], 2, 3, 1);
    // dense head
    k_dense<<<DDENSE / 128, 128>>>(2, Wd, bd, out);
}